// round 5
// baseline (speedup 1.0000x reference)
#include <cuda_runtime.h>

// Problem constants
#define NB 128
#define NT 16
#define NTO 32
#define NJ 25

// ---------------------------------------------------------------------------
// Scratch (device globals)
// ---------------------------------------------------------------------------
__device__ float g_Wqs[8 * 256];     // reduced Wq (s-half channel sums) [m][i]
__device__ float g_bqs[8];
__device__ float g_Wks[8 * 256];
__device__ float g_bks[8];
__device__ float g_WsumT[256 * 32];  // [i][c] : sum_m Wv[m*64+c][i]
__device__ float g_WpartT[8][256 * 32]; // [p][i][c] : sum_{m<p} Wv[m*64+c][i]
__device__ float g_BS[32];           // sum_m bv[m*64+c]
__device__ float g_qs[NB * 6400];    // qs_sum  [b][g]
__device__ float g_ksp[NB * 3200];   // ks_pre  [b][g]
__device__ float g_kss[NB * 6400];   // ks_sum
__device__ float g_Pn[NB * 129 * 256];  // prefix rows at endpoints [b][qq][i]
__device__ float g_E[NB * 129 * 32];    // telescoped cums [b][qq][c]
__device__ float g_Vt[51200 * 256];  // t-half V GEMM result (compact cols)
__device__ float g_vs[NB * 8 * 32 * 32]; // vs_sum [b][h][to][c]
__device__ float g_vt[NB * 8 * 25 * 32]; // vt_sum [b][h][j][c]

// ---------------------------------------------------------------------------
// f32x2 packed helpers (sm_100+)
// ---------------------------------------------------------------------------
__device__ __forceinline__ unsigned long long pack2(float x, float y) {
    unsigned long long r;
    asm("mov.b64 %0, {%1, %2};" : "=l"(r) : "r"(__float_as_uint(x)), "r"(__float_as_uint(y)));
    return r;
}
__device__ __forceinline__ unsigned long long dup2(float x) {
    unsigned long long r;
    asm("mov.b64 %0, {%1, %1};" : "=l"(r) : "r"(__float_as_uint(x)));
    return r;
}
__device__ __forceinline__ float2 unpack2(unsigned long long v) {
    unsigned int lo, hi;
    asm("mov.b64 {%0, %1}, %2;" : "=r"(lo), "=r"(hi) : "l"(v));
    return make_float2(__uint_as_float(lo), __uint_as_float(hi));
}
#define FMA2(acc, a2, b2) \
    asm("fma.rn.f32x2 %0, %1, %2, %0;" : "+l"(acc) : "l"(a2), "l"(b2))

// ---------------------------------------------------------------------------
// Kernel: reduced Q/K weights
// ---------------------------------------------------------------------------
__global__ void prep_weights(const float* __restrict__ Wq, const float* __restrict__ bq,
                             const float* __restrict__ Wk, const float* __restrict__ bk) {
    int idx = blockIdx.x * 256 + threadIdx.x;
    if (idx >= 4096) return;
    int set = idx >> 11;
    int m = (idx >> 8) & 7;
    int i = idx & 255;
    const float* W = set ? Wk : Wq;
    float s = 0.f;
    #pragma unroll
    for (int c = 0; c < 32; c++) s += W[(m * 64 + c) * 256 + i];
    if (set) g_Wks[m * 256 + i] = s; else g_Wqs[m * 256 + i] = s;
    if (i == 0) {
        const float* bb = set ? bk : bq;
        float t = 0.f;
        #pragma unroll
        for (int c = 0; c < 32; c++) t += bb[m * 64 + c];
        if (set) g_bks[m] = t; else g_bqs[m] = t;
    }
}

// ---------------------------------------------------------------------------
// Kernel: V-weight prefix tables for the s-half telescope
// ---------------------------------------------------------------------------
__global__ void prep_vweights(const float* __restrict__ Wv, const float* __restrict__ bv) {
    int idx = blockIdx.x * 256 + threadIdx.x; // 0..8191
    if (idx >= 8192) return;
    int c = idx & 31, i = idx >> 5;
    float acc = 0.f;
    #pragma unroll
    for (int m = 0; m < 8; m++) {
        g_WpartT[m][i * 32 + c] = acc;
        acc += Wv[(m * 64 + c) * 256 + i];
    }
    g_WsumT[i * 32 + c] = acc;
    if (i == 0) {
        float s = 0.f;
        #pragma unroll
        for (int m = 0; m < 8; m++) s += bv[m * 64 + c];
        g_BS[c] = s;
    }
}

// ---------------------------------------------------------------------------
// Kernel: row prefix of enc, stored at the 129 telescope endpoints per batch.
// CTA per b, thread = channel i.
// ---------------------------------------------------------------------------
__global__ void __launch_bounds__(256) enc_prefix(const float* __restrict__ enc) {
    int b = blockIdx.x;
    int i = threadIdx.x;
    const float* e = enc + (size_t)b * 400 * 256 + i;
    float* Pn = g_Pn + (size_t)b * 129 * 256;
    Pn[i] = 0.f; // qq = 0
    float acc = 0.f;
    for (int r = 0; r < 400; r++) {
        acc += e[(size_t)r * 256];
        // checkpoint if exists qq with (25qq>>3)-1 == r  <=>  25qq in [8r+8, 8r+16)
        int qq = (8 * r + 32) / 25;
        int v = 25 * qq;
        if (v >= 8 * r + 8 && v < 8 * r + 16)
            Pn[(size_t)qq * 256 + i] = acc;
    }
}

// ---------------------------------------------------------------------------
// Kernel: E[b,qq,c] = Pn[b,qq]·WsumT[:,c] + enc[row R]·WpartT[p][:,c]
// warp per (b,qq), lane = c.
// ---------------------------------------------------------------------------
__global__ void __launch_bounds__(256) e_kernel(const float* __restrict__ enc) {
    int id = blockIdx.x * 8 + (threadIdx.x >> 5);
    if (id >= NB * 129) return;
    int c = threadIdx.x & 31;
    int b = id / 129, qq = id - b * 129;
    const float* Pn = g_Pn + (size_t)id * 256;
    float acc = 0.f;
    for (int i = 0; i < 256; i++) acc += Pn[i] * g_WsumT[i * 32 + c];
    int p = qq & 7;
    if (p) {
        int R = (25 * qq) >> 3;
        const float* er = enc + ((size_t)b * 400 + R) * 256;
        const float* Wp = g_WpartT[p];
        for (int i = 0; i < 256; i++) acc += er[i] * Wp[i * 32 + c];
    }
    g_E[(size_t)id * 32 + c] = acc;
}

// ---------------------------------------------------------------------------
// Kernel: vs_sum[b,h,to,c] = sum_t Wconv[to,t]*U[b,h*16+t,c] + 25*bconv[to]
//   U[q,c] = E[q+1]-E[q] + 3*BS[c] + bv[(q&7)*64+c]
// ---------------------------------------------------------------------------
__global__ void __launch_bounds__(256) vs_assemble(const float* __restrict__ Wconv,
                                                   const float* __restrict__ bconv,
                                                   const float* __restrict__ bv) {
    int idx = blockIdx.x * 256 + threadIdx.x;
    if (idx >= NB * 8 * 32 * 32) return;
    int c = idx & 31;
    int to = (idx >> 5) & 31;
    int h = (idx >> 10) & 7;
    int b = idx >> 13;
    const float* Eb = g_E + (size_t)b * 129 * 32;
    float bs3 = 3.f * g_BS[c];
    float acc = 25.f * bconv[to];
    #pragma unroll
    for (int t = 0; t < 16; t++) {
        int q = h * 16 + t;
        float U = Eb[(q + 1) * 32 + c] - Eb[q * 32 + c] + bs3 + bv[(q & 7) * 64 + c];
        acc += Wconv[to * 16 + t] * U;
    }
    g_vs[idx] = acc;
}

// ---------------------------------------------------------------------------
// Kernel: reduced-weight row GEMM (q and k paths)
// ---------------------------------------------------------------------------
template <int WHICH>
__global__ void __launch_bounds__(256) row_reduce(const float* __restrict__ src) {
    __shared__ float sW[2048];
    for (int i = threadIdx.x; i < 2048; i += 256)
        sW[i] = (WHICH == 0) ? g_Wqs[i] : g_Wks[i];
    __syncthreads();
    int warp = threadIdx.x >> 5, lane = threadIdx.x & 31;
    int R = blockIdx.x * 8 + warp;
    const float* xr = src + (size_t)R * 256;
    float p[8] = {0.f, 0.f, 0.f, 0.f, 0.f, 0.f, 0.f, 0.f};
    for (int i = lane; i < 256; i += 32) {
        float xv = xr[i];
        #pragma unroll
        for (int m = 0; m < 8; m++) p[m] += xv * sW[m * 256 + i];
    }
    #pragma unroll
    for (int m = 0; m < 8; m++) {
        #pragma unroll
        for (int off = 16; off; off >>= 1)
            p[m] += __shfl_down_sync(0xffffffffu, p[m], off);
    }
    if (lane == 0) {
        float* dst = (WHICH == 0) ? g_qs : g_ksp;
        const float* bs = (WHICH == 0) ? g_bqs : g_bks;
        #pragma unroll
        for (int m = 0; m < 8; m++) dst[(size_t)R * 8 + m] = p[m] + bs[m];
    }
}

// ---------------------------------------------------------------------------
// Kernel: K temporal conv
// ---------------------------------------------------------------------------
__global__ void k_conv(const float* __restrict__ Wconv, const float* __restrict__ bconv) {
    int idx = blockIdx.x * blockDim.x + threadIdx.x;
    if (idx >= NB * 6400) return;
    int b = idx / 6400;
    int g = idx - b * 6400;
    int h = g / 800;
    int rem = g - h * 800;
    int to = rem / 25;
    int j = rem - to * 25;
    const float* kp = g_ksp + b * 3200 + h * 400 + j;
    float s = 32.0f * bconv[to];
    #pragma unroll
    for (int t = 0; t < 16; t++) s += Wconv[to * 16 + t] * kp[t * 25];
    g_kss[idx] = s;
}

// ---------------------------------------------------------------------------
// Kernel: t-half V GEMM with packed f32x2 FMA.
// C[r, o'] = enc[r,:]·Wv[wmap(o'),:] + bv[wmap(o')], wmap(o')=(o'>>5)*64+32+(o'&31)
// M=51200, N=256, K=256. Tiles 128x128x8, thread tile 8x8 (4 packed pairs).
// ---------------------------------------------------------------------------
__global__ void __launch_bounds__(256) v_gemm_t(const float* __restrict__ A,
                                                const float* __restrict__ W,
                                                const float* __restrict__ bv) {
    __shared__ float As[8][128];
    __shared__ float Bs[8][128];
    int tm = blockIdx.y, tn = blockIdx.x; // tn in {0,1}
    int tid = threadIdx.x;
    int tr = tid >> 4, tc = tid & 15;
    const float* Ab = A + (size_t)tm * 128 * 256;

    int lrow = tid >> 1, lk = (tid & 1) * 4;
    int wcol = tn * 128 + lrow;
    int wrow = ((wcol >> 5) << 6) + 32 + (wcol & 31);
    const float* Wr = W + (size_t)wrow * 256;
    const float* Ar = Ab + (size_t)lrow * 256;

    unsigned long long acc2[8][4];
    #pragma unroll
    for (int i = 0; i < 8; i++)
        #pragma unroll
        for (int jp = 0; jp < 4; jp++) acc2[i][jp] = 0ull;

    for (int k0 = 0; k0 < 256; k0 += 8) {
        float4 av = *reinterpret_cast<const float4*>(Ar + k0 + lk);
        float4 wv = *reinterpret_cast<const float4*>(Wr + k0 + lk);
        As[lk + 0][lrow] = av.x; As[lk + 1][lrow] = av.y;
        As[lk + 2][lrow] = av.z; As[lk + 3][lrow] = av.w;
        Bs[lk + 0][lrow] = wv.x; Bs[lk + 1][lrow] = wv.y;
        Bs[lk + 2][lrow] = wv.z; Bs[lk + 3][lrow] = wv.w;
        __syncthreads();
        #pragma unroll
        for (int k = 0; k < 8; k++) {
            const float4 a0 = *reinterpret_cast<const float4*>(&As[k][tr * 8]);
            const float4 a1 = *reinterpret_cast<const float4*>(&As[k][tr * 8 + 4]);
            const float4 b0 = *reinterpret_cast<const float4*>(&Bs[k][tc * 8]);
            const float4 b1 = *reinterpret_cast<const float4*>(&Bs[k][tc * 8 + 4]);
            unsigned long long bp0 = pack2(b0.x, b0.y);
            unsigned long long bp1 = pack2(b0.z, b0.w);
            unsigned long long bp2 = pack2(b1.x, b1.y);
            unsigned long long bp3 = pack2(b1.z, b1.w);
            float aa[8] = {a0.x, a0.y, a0.z, a0.w, a1.x, a1.y, a1.z, a1.w};
            #pragma unroll
            for (int i = 0; i < 8; i++) {
                unsigned long long ad = dup2(aa[i]);
                FMA2(acc2[i][0], ad, bp0);
                FMA2(acc2[i][1], ad, bp1);
                FMA2(acc2[i][2], ad, bp2);
                FMA2(acc2[i][3], ad, bp3);
            }
        }
        __syncthreads();
    }

    int gr0 = tm * 128 + tr * 8;
    int gc0 = tn * 128 + tc * 8;
    float bvr[8];
    #pragma unroll
    for (int j = 0; j < 8; j++) {
        int col = gc0 + j;
        bvr[j] = bv[((col >> 5) << 6) + 32 + (col & 31)];
    }
    #pragma unroll
    for (int i = 0; i < 8; i++) {
        float2 r0 = unpack2(acc2[i][0]);
        float2 r1 = unpack2(acc2[i][1]);
        float2 r2 = unpack2(acc2[i][2]);
        float2 r3 = unpack2(acc2[i][3]);
        float* Crow = g_Vt + (size_t)(gr0 + i) * 256 + gc0;
        float4 v0 = make_float4(r0.x + bvr[0], r0.y + bvr[1], r1.x + bvr[2], r1.y + bvr[3]);
        float4 v1 = make_float4(r2.x + bvr[4], r2.y + bvr[5], r3.x + bvr[6], r3.y + bvr[7]);
        *reinterpret_cast<float4*>(Crow) = v0;
        *reinterpret_cast<float4*>(Crow + 4) = v1;
    }
}

// ---------------------------------------------------------------------------
// Kernel: vt reduction from compact t-half V.
// vt[b,h,j,c] = sum_t2 Vt[b*400 + (g>>3)][ (g&7)*32 + c ],  g=400h+25t2+j
// ---------------------------------------------------------------------------
__global__ void __launch_bounds__(256) vt_reduce() {
    int bh = blockIdx.x;
    int b = bh >> 3, h = bh & 7;
    int tid = threadIdx.x;
    const float* Vb = g_Vt + (size_t)b * 400 * 256;
    for (int s = tid; s < 800; s += 256) {
        int j = s >> 5, c = s & 31;
        float acc = 0.f;
        #pragma unroll
        for (int t2 = 0; t2 < 16; t2++) {
            int g = 400 * h + 25 * t2 + j;
            acc += Vb[(size_t)(g >> 3) * 256 + (g & 7) * 32 + c];
        }
        g_vt[(size_t)bh * 800 + s] = acc;
    }
}

// ---------------------------------------------------------------------------
// Kernel: emit output (diag softmax * vs ; vt passthrough)
// ---------------------------------------------------------------------------
__global__ void __launch_bounds__(256) emit_out(const int* __restrict__ mask_s,
                                                float* __restrict__ out) {
    __shared__ float s_qs[800], s_kss[800], s_vs[1024], s_vt[800];
    int bh = blockIdx.x;
    int b = bh >> 3, h = bh & 7;
    int tid = threadIdx.x;
    for (int i = tid; i < 800; i += 256) {
        s_qs[i]  = g_qs[b * 6400 + h * 800 + i];
        s_kss[i] = g_kss[b * 6400 + h * 800 + i];
        s_vt[i]  = g_vt[(size_t)bh * 800 + i];
    }
    for (int i = tid; i < 1024; i += 256) s_vs[i] = g_vs[(size_t)bh * 1024 + i];
    __syncthreads();

    int warp = tid >> 5, lane = tid & 31;
    for (int it = warp; it < 800; it += 8) {
        int to = it / 25, j = it - to * 25;
        float a = s_qs[it];
        float sc;
        if (lane < 25) {
            int mk = mask_s[(to * 25 + j) * 25 + lane];
            sc = mk ? a * s_kss[to * 25 + lane] : -1.0e9f;
        } else {
            sc = -3.0e38f;
        }
        float mx = sc;
        #pragma unroll
        for (int off = 16; off; off >>= 1)
            mx = fmaxf(mx, __shfl_xor_sync(0xffffffffu, mx, off));
        float e = (lane < 25) ? expf(sc - mx) : 0.f;
        float ssum = e;
        #pragma unroll
        for (int off = 16; off; off >>= 1)
            ssum += __shfl_xor_sync(0xffffffffu, ssum, off);
        float diag = __shfl_sync(0xffffffffu, e, j) / ssum;

        int obase = ((b * 32 + to) * 25 + j) * 512 + h * 64;
        out[obase + lane]      = diag * s_vs[to * 32 + lane];
        out[obase + 32 + lane] = s_vt[j * 32 + lane];
    }
}

// ---------------------------------------------------------------------------
extern "C" void kernel_launch(void* const* d_in, const int* in_sizes, int n_in,
                              void* d_out, int out_size) {
    const float* x      = (const float*)d_in[0];
    const float* enc    = (const float*)d_in[1];
    const int*   mask_s = (const int*)d_in[2];
    // d_in[3] = mask_t (unused: temporal softmax rows sum to 1)
    const float* Wq     = (const float*)d_in[4];
    const float* bq     = (const float*)d_in[5];
    const float* Wk     = (const float*)d_in[6];
    const float* bk     = (const float*)d_in[7];
    const float* Wv     = (const float*)d_in[8];
    const float* bv     = (const float*)d_in[9];
    const float* Wconv  = (const float*)d_in[10];
    const float* bconv  = (const float*)d_in[11];
    float* out = (float*)d_out;

    prep_weights<<<16, 256>>>(Wq, bq, Wk, bk);
    prep_vweights<<<32, 256>>>(Wv, bv);
    enc_prefix<<<128, 256>>>(enc);
    row_reduce<0><<<12800, 256>>>(x);
    row_reduce<1><<<6400, 256>>>(enc);
    k_conv<<<3200, 256>>>(Wconv, bconv);
    e_kernel<<<2064, 256>>>(enc);
    vs_assemble<<<4096, 256>>>(Wconv, bconv, bv);
    v_gemm_t<<<dim3(2, 400), 256>>>(enc, Wv, bv);
    vt_reduce<<<1024, 256>>>();
    emit_out<<<1024, 256>>>(mask_s, out);
    (void)in_sizes; (void)n_in; (void)out_size;
}

// round 6
// speedup vs baseline: 1.0084x; 1.0084x over previous
#include <cuda_runtime.h>

// Problem constants
#define NB 128
#define NT 16
#define NTO 32
#define NJ 25

// ---------------------------------------------------------------------------
// Scratch (device globals)
// ---------------------------------------------------------------------------
__device__ float g_Wqs[8 * 256];     // reduced Wq (s-half channel sums) [m][i]
__device__ float g_bqs[8];
__device__ float g_Wks[8 * 256];
__device__ float g_bks[8];
__device__ float g_WsumT[256 * 32];  // [i][c] : sum_m Wv[m*64+c][i]
__device__ float g_WpartT[8][256 * 32]; // [p][i][c] : sum_{m<p} Wv[m*64+c][i]
__device__ float g_BS[32];           // sum_m bv[m*64+c]
__device__ float g_qs[NB * 6400];    // qs_sum  [b][g]
__device__ float g_ksp[NB * 3200];   // ks_pre  [b][g]
__device__ float g_kss[NB * 6400];   // ks_sum
__device__ float g_Pn[NB * 129 * 256];  // prefix rows at endpoints [b][qq][i]
__device__ float g_E[NB * 129 * 32];    // telescoped cums [b][qq][c]
__device__ float g_Vt[51200 * 256];  // t-half V GEMM result (compact cols)
__device__ float g_vs[NB * 8 * 32 * 32]; // vs_sum [b][h][to][c]
__device__ float g_vt[NB * 8 * 25 * 32]; // vt_sum [b][h][j][c]

// ---------------------------------------------------------------------------
// f32x2 packed helpers (sm_100+)
// ---------------------------------------------------------------------------
__device__ __forceinline__ unsigned long long pack2(float x, float y) {
    unsigned long long r;
    asm("mov.b64 %0, {%1, %2};" : "=l"(r) : "r"(__float_as_uint(x)), "r"(__float_as_uint(y)));
    return r;
}
__device__ __forceinline__ unsigned long long dup2(float x) {
    unsigned long long r;
    asm("mov.b64 %0, {%1, %1};" : "=l"(r) : "r"(__float_as_uint(x)));
    return r;
}
__device__ __forceinline__ float2 unpack2(unsigned long long v) {
    unsigned int lo, hi;
    asm("mov.b64 {%0, %1}, %2;" : "=r"(lo), "=r"(hi) : "l"(v));
    return make_float2(__uint_as_float(lo), __uint_as_float(hi));
}
#define FMA2(acc, a2, b2) \
    asm("fma.rn.f32x2 %0, %1, %2, %0;" : "+l"(acc) : "l"(a2), "l"(b2))

// ---------------------------------------------------------------------------
// Kernel: reduced Q/K weights
// ---------------------------------------------------------------------------
__global__ void prep_weights(const float* __restrict__ Wq, const float* __restrict__ bq,
                             const float* __restrict__ Wk, const float* __restrict__ bk) {
    int idx = blockIdx.x * 256 + threadIdx.x;
    if (idx >= 4096) return;
    int set = idx >> 11;
    int m = (idx >> 8) & 7;
    int i = idx & 255;
    const float* W = set ? Wk : Wq;
    float s = 0.f;
    #pragma unroll
    for (int c = 0; c < 32; c++) s += W[(m * 64 + c) * 256 + i];
    if (set) g_Wks[m * 256 + i] = s; else g_Wqs[m * 256 + i] = s;
    if (i == 0) {
        const float* bb = set ? bk : bq;
        float t = 0.f;
        #pragma unroll
        for (int c = 0; c < 32; c++) t += bb[m * 64 + c];
        if (set) g_bks[m] = t; else g_bqs[m] = t;
    }
}

// ---------------------------------------------------------------------------
// Kernel: V-weight prefix tables for the s-half telescope
// ---------------------------------------------------------------------------
__global__ void prep_vweights(const float* __restrict__ Wv, const float* __restrict__ bv) {
    int idx = blockIdx.x * 256 + threadIdx.x; // 0..8191
    if (idx >= 8192) return;
    int c = idx & 31, i = idx >> 5;
    float acc = 0.f;
    #pragma unroll
    for (int m = 0; m < 8; m++) {
        g_WpartT[m][i * 32 + c] = acc;
        acc += Wv[(m * 64 + c) * 256 + i];
    }
    g_WsumT[i * 32 + c] = acc;
    if (i == 0) {
        float s = 0.f;
        #pragma unroll
        for (int m = 0; m < 8; m++) s += bv[m * 64 + c];
        g_BS[c] = s;
    }
}

// ---------------------------------------------------------------------------
// Kernel: row prefix of enc, stored at the 129 telescope endpoints per batch.
// CTA per b, thread = channel i.
// ---------------------------------------------------------------------------
__global__ void __launch_bounds__(256) enc_prefix(const float* __restrict__ enc) {
    int b = blockIdx.x;
    int i = threadIdx.x;
    const float* e = enc + (size_t)b * 400 * 256 + i;
    float* Pn = g_Pn + (size_t)b * 129 * 256;
    Pn[i] = 0.f; // qq = 0
    float acc = 0.f;
    for (int r = 0; r < 400; r++) {
        acc += e[(size_t)r * 256];
        // checkpoint if exists qq with (25qq>>3)-1 == r  <=>  25qq in [8r+8, 8r+16)
        int qq = (8 * r + 32) / 25;
        int v = 25 * qq;
        if (v >= 8 * r + 8 && v < 8 * r + 16)
            Pn[(size_t)qq * 256 + i] = acc;
    }
}

// ---------------------------------------------------------------------------
// Kernel: E[b,qq,c] = Pn[b,qq]·WsumT[:,c] + enc[row R]·WpartT[p][:,c]
// warp per (b,qq), lane = c.
// ---------------------------------------------------------------------------
__global__ void __launch_bounds__(256) e_kernel(const float* __restrict__ enc) {
    int id = blockIdx.x * 8 + (threadIdx.x >> 5);
    if (id >= NB * 129) return;
    int c = threadIdx.x & 31;
    int b = id / 129, qq = id - b * 129;
    const float* Pn = g_Pn + (size_t)id * 256;
    float acc = 0.f;
    for (int i = 0; i < 256; i++) acc += Pn[i] * g_WsumT[i * 32 + c];
    int p = qq & 7;
    if (p) {
        int R = (25 * qq) >> 3;
        const float* er = enc + ((size_t)b * 400 + R) * 256;
        const float* Wp = g_WpartT[p];
        for (int i = 0; i < 256; i++) acc += er[i] * Wp[i * 32 + c];
    }
    g_E[(size_t)id * 32 + c] = acc;
}

// ---------------------------------------------------------------------------
// Kernel: vs_sum[b,h,to,c] = sum_t Wconv[to,t]*U[b,h*16+t,c] + 25*bconv[to]
//   U[q,c] = E[q+1]-E[q] + 3*BS[c] + bv[(q&7)*64+c]
// ---------------------------------------------------------------------------
__global__ void __launch_bounds__(256) vs_assemble(const float* __restrict__ Wconv,
                                                   const float* __restrict__ bconv,
                                                   const float* __restrict__ bv) {
    int idx = blockIdx.x * 256 + threadIdx.x;
    if (idx >= NB * 8 * 32 * 32) return;
    int c = idx & 31;
    int to = (idx >> 5) & 31;
    int h = (idx >> 10) & 7;
    int b = idx >> 13;
    const float* Eb = g_E + (size_t)b * 129 * 32;
    float bs3 = 3.f * g_BS[c];
    float acc = 25.f * bconv[to];
    #pragma unroll
    for (int t = 0; t < 16; t++) {
        int q = h * 16 + t;
        float U = Eb[(q + 1) * 32 + c] - Eb[q * 32 + c] + bs3 + bv[(q & 7) * 64 + c];
        acc += Wconv[to * 16 + t] * U;
    }
    g_vs[idx] = acc;
}

// ---------------------------------------------------------------------------
// Kernel: reduced-weight row GEMM (q and k paths)
// ---------------------------------------------------------------------------
template <int WHICH>
__global__ void __launch_bounds__(256) row_reduce(const float* __restrict__ src) {
    __shared__ float sW[2048];
    for (int i = threadIdx.x; i < 2048; i += 256)
        sW[i] = (WHICH == 0) ? g_Wqs[i] : g_Wks[i];
    __syncthreads();
    int warp = threadIdx.x >> 5, lane = threadIdx.x & 31;
    int R = blockIdx.x * 8 + warp;
    const float* xr = src + (size_t)R * 256;
    float p[8] = {0.f, 0.f, 0.f, 0.f, 0.f, 0.f, 0.f, 0.f};
    for (int i = lane; i < 256; i += 32) {
        float xv = xr[i];
        #pragma unroll
        for (int m = 0; m < 8; m++) p[m] += xv * sW[m * 256 + i];
    }
    #pragma unroll
    for (int m = 0; m < 8; m++) {
        #pragma unroll
        for (int off = 16; off; off >>= 1)
            p[m] += __shfl_down_sync(0xffffffffu, p[m], off);
    }
    if (lane == 0) {
        float* dst = (WHICH == 0) ? g_qs : g_ksp;
        const float* bs = (WHICH == 0) ? g_bqs : g_bks;
        #pragma unroll
        for (int m = 0; m < 8; m++) dst[(size_t)R * 8 + m] = p[m] + bs[m];
    }
}

// ---------------------------------------------------------------------------
// Kernel: K temporal conv
// ---------------------------------------------------------------------------
__global__ void k_conv(const float* __restrict__ Wconv, const float* __restrict__ bconv) {
    int idx = blockIdx.x * blockDim.x + threadIdx.x;
    if (idx >= NB * 6400) return;
    int b = idx / 6400;
    int g = idx - b * 6400;
    int h = g / 800;
    int rem = g - h * 800;
    int to = rem / 25;
    int j = rem - to * 25;
    const float* kp = g_ksp + b * 3200 + h * 400 + j;
    float s = 32.0f * bconv[to];
    #pragma unroll
    for (int t = 0; t < 16; t++) s += Wconv[to * 16 + t] * kp[t * 25];
    g_kss[idx] = s;
}

// ---------------------------------------------------------------------------
// Kernel: t-half V GEMM with packed f32x2 FMA.
// C[r, o'] = enc[r,:]·Wv[wmap(o'),:] + bv[wmap(o')], wmap(o')=(o'>>5)*64+32+(o'&31)
// M=51200, N=256, K=256. Tiles 128x128x8, thread tile 8x8 (4 packed pairs).
// ---------------------------------------------------------------------------
__global__ void __launch_bounds__(256) v_gemm_t(const float* __restrict__ A,
                                                const float* __restrict__ W,
                                                const float* __restrict__ bv) {
    __shared__ float As[8][128];
    __shared__ float Bs[8][128];
    int tm = blockIdx.y, tn = blockIdx.x; // tn in {0,1}
    int tid = threadIdx.x;
    int tr = tid >> 4, tc = tid & 15;
    const float* Ab = A + (size_t)tm * 128 * 256;

    int lrow = tid >> 1, lk = (tid & 1) * 4;
    int wcol = tn * 128 + lrow;
    int wrow = ((wcol >> 5) << 6) + 32 + (wcol & 31);
    const float* Wr = W + (size_t)wrow * 256;
    const float* Ar = Ab + (size_t)lrow * 256;

    unsigned long long acc2[8][4];
    #pragma unroll
    for (int i = 0; i < 8; i++)
        #pragma unroll
        for (int jp = 0; jp < 4; jp++) acc2[i][jp] = 0ull;

    for (int k0 = 0; k0 < 256; k0 += 8) {
        float4 av = *reinterpret_cast<const float4*>(Ar + k0 + lk);
        float4 wv = *reinterpret_cast<const float4*>(Wr + k0 + lk);
        As[lk + 0][lrow] = av.x; As[lk + 1][lrow] = av.y;
        As[lk + 2][lrow] = av.z; As[lk + 3][lrow] = av.w;
        Bs[lk + 0][lrow] = wv.x; Bs[lk + 1][lrow] = wv.y;
        Bs[lk + 2][lrow] = wv.z; Bs[lk + 3][lrow] = wv.w;
        __syncthreads();
        #pragma unroll
        for (int k = 0; k < 8; k++) {
            const float4 a0 = *reinterpret_cast<const float4*>(&As[k][tr * 8]);
            const float4 a1 = *reinterpret_cast<const float4*>(&As[k][tr * 8 + 4]);
            const float4 b0 = *reinterpret_cast<const float4*>(&Bs[k][tc * 8]);
            const float4 b1 = *reinterpret_cast<const float4*>(&Bs[k][tc * 8 + 4]);
            unsigned long long bp0 = pack2(b0.x, b0.y);
            unsigned long long bp1 = pack2(b0.z, b0.w);
            unsigned long long bp2 = pack2(b1.x, b1.y);
            unsigned long long bp3 = pack2(b1.z, b1.w);
            float aa[8] = {a0.x, a0.y, a0.z, a0.w, a1.x, a1.y, a1.z, a1.w};
            #pragma unroll
            for (int i = 0; i < 8; i++) {
                unsigned long long ad = dup2(aa[i]);
                FMA2(acc2[i][0], ad, bp0);
                FMA2(acc2[i][1], ad, bp1);
                FMA2(acc2[i][2], ad, bp2);
                FMA2(acc2[i][3], ad, bp3);
            }
        }
        __syncthreads();
    }

    int gr0 = tm * 128 + tr * 8;
    int gc0 = tn * 128 + tc * 8;
    float bvr[8];
    #pragma unroll
    for (int j = 0; j < 8; j++) {
        int col = gc0 + j;
        bvr[j] = bv[((col >> 5) << 6) + 32 + (col & 31)];
    }
    #pragma unroll
    for (int i = 0; i < 8; i++) {
        float2 r0 = unpack2(acc2[i][0]);
        float2 r1 = unpack2(acc2[i][1]);
        float2 r2 = unpack2(acc2[i][2]);
        float2 r3 = unpack2(acc2[i][3]);
        float* Crow = g_Vt + (size_t)(gr0 + i) * 256 + gc0;
        float4 v0 = make_float4(r0.x + bvr[0], r0.y + bvr[1], r1.x + bvr[2], r1.y + bvr[3]);
        float4 v1 = make_float4(r2.x + bvr[4], r2.y + bvr[5], r3.x + bvr[6], r3.y + bvr[7]);
        *reinterpret_cast<float4*>(Crow) = v0;
        *reinterpret_cast<float4*>(Crow + 4) = v1;
    }
}

// ---------------------------------------------------------------------------
// Kernel: vt reduction from compact t-half V.
// vt[b,h,j,c] = sum_t2 Vt[b*400 + (g>>3)][ (g&7)*32 + c ],  g=400h+25t2+j
// ---------------------------------------------------------------------------
__global__ void __launch_bounds__(256) vt_reduce() {
    int bh = blockIdx.x;
    int b = bh >> 3, h = bh & 7;
    int tid = threadIdx.x;
    const float* Vb = g_Vt + (size_t)b * 400 * 256;
    for (int s = tid; s < 800; s += 256) {
        int j = s >> 5, c = s & 31;
        float acc = 0.f;
        #pragma unroll
        for (int t2 = 0; t2 < 16; t2++) {
            int g = 400 * h + 25 * t2 + j;
            acc += Vb[(size_t)(g >> 3) * 256 + (g & 7) * 32 + c];
        }
        g_vt[(size_t)bh * 800 + s] = acc;
    }
}

// ---------------------------------------------------------------------------
// Kernel: emit output (diag softmax * vs ; vt passthrough)
// ---------------------------------------------------------------------------
__global__ void __launch_bounds__(256) emit_out(const int* __restrict__ mask_s,
                                                float* __restrict__ out) {
    __shared__ float s_qs[800], s_kss[800], s_vs[1024], s_vt[800];
    int bh = blockIdx.x;
    int b = bh >> 3, h = bh & 7;
    int tid = threadIdx.x;
    for (int i = tid; i < 800; i += 256) {
        s_qs[i]  = g_qs[b * 6400 + h * 800 + i];
        s_kss[i] = g_kss[b * 6400 + h * 800 + i];
        s_vt[i]  = g_vt[(size_t)bh * 800 + i];
    }
    for (int i = tid; i < 1024; i += 256) s_vs[i] = g_vs[(size_t)bh * 1024 + i];
    __syncthreads();

    int warp = tid >> 5, lane = tid & 31;
    for (int it = warp; it < 800; it += 8) {
        int to = it / 25, j = it - to * 25;
        float a = s_qs[it];
        float sc;
        if (lane < 25) {
            int mk = mask_s[(to * 25 + j) * 25 + lane];
            sc = mk ? a * s_kss[to * 25 + lane] : -1.0e9f;
        } else {
            sc = -3.0e38f;
        }
        float mx = sc;
        #pragma unroll
        for (int off = 16; off; off >>= 1)
            mx = fmaxf(mx, __shfl_xor_sync(0xffffffffu, mx, off));
        float e = (lane < 25) ? expf(sc - mx) : 0.f;
        float ssum = e;
        #pragma unroll
        for (int off = 16; off; off >>= 1)
            ssum += __shfl_xor_sync(0xffffffffu, ssum, off);
        float diag = __shfl_sync(0xffffffffu, e, j) / ssum;

        int obase = ((b * 32 + to) * 25 + j) * 512 + h * 64;
        out[obase + lane]      = diag * s_vs[to * 32 + lane];
        out[obase + 32 + lane] = s_vt[j * 32 + lane];
    }
}

// ---------------------------------------------------------------------------
extern "C" void kernel_launch(void* const* d_in, const int* in_sizes, int n_in,
                              void* d_out, int out_size) {
    const float* x      = (const float*)d_in[0];
    const float* enc    = (const float*)d_in[1];
    const int*   mask_s = (const int*)d_in[2];
    // d_in[3] = mask_t (unused: temporal softmax rows sum to 1)
    const float* Wq     = (const float*)d_in[4];
    const float* bq     = (const float*)d_in[5];
    const float* Wk     = (const float*)d_in[6];
    const float* bk     = (const float*)d_in[7];
    const float* Wv     = (const float*)d_in[8];
    const float* bv     = (const float*)d_in[9];
    const float* Wconv  = (const float*)d_in[10];
    const float* bconv  = (const float*)d_in[11];
    float* out = (float*)d_out;

    prep_weights<<<16, 256>>>(Wq, bq, Wk, bk);
    prep_vweights<<<32, 256>>>(Wv, bv);
    enc_prefix<<<128, 256>>>(enc);
    row_reduce<0><<<12800, 256>>>(x);
    row_reduce<1><<<6400, 256>>>(enc);
    k_conv<<<3200, 256>>>(Wconv, bconv);
    e_kernel<<<2064, 256>>>(enc);
    vs_assemble<<<4096, 256>>>(Wconv, bconv, bv);
    v_gemm_t<<<dim3(2, 400), 256>>>(enc, Wv, bv);
    vt_reduce<<<1024, 256>>>();
    emit_out<<<1024, 256>>>(mask_s, out);
    (void)in_sizes; (void)n_in; (void)out_size;
}

// round 7
// speedup vs baseline: 1.0095x; 1.0011x over previous
#include <cuda_runtime.h>

// Problem constants
#define NB 128
#define NT 16
#define NTO 32
#define NJ 25

// ---------------------------------------------------------------------------
// Scratch (device globals)
// ---------------------------------------------------------------------------
__device__ float g_Wqs[8 * 256];     // reduced Wq (s-half channel sums) [m][i]
__device__ float g_bqs[8];
__device__ float g_Wks[8 * 256];
__device__ float g_bks[8];
__device__ float g_WsumT[256 * 32];  // [i][c] : sum_m Wv[m*64+c][i]
__device__ float g_WpartT[8][256 * 32]; // [p][i][c] : sum_{m<p} Wv[m*64+c][i]
__device__ float g_BS[32];           // sum_m bv[m*64+c]
__device__ float g_qs[NB * 6400];    // qs_sum  [b][g]
__device__ float g_ksp[NB * 3200];   // ks_pre  [b][g]
__device__ float g_kss[NB * 6400];   // ks_sum
__device__ float g_Pn[NB * 129 * 256];  // prefix rows at endpoints [b][qq][i]
__device__ float g_E[NB * 129 * 32];    // telescoped cums [b][qq][c]
__device__ float g_Vt[51200 * 256];  // t-half V GEMM result (compact cols)
__device__ float g_vs[NB * 8 * 32 * 32]; // vs_sum [b][h][to][c]
__device__ float g_vt[NB * 8 * 25 * 32]; // vt_sum [b][h][j][c]

// ---------------------------------------------------------------------------
// f32x2 packed helpers (sm_100+)
// ---------------------------------------------------------------------------
__device__ __forceinline__ unsigned long long pack2(float x, float y) {
    unsigned long long r;
    asm("mov.b64 %0, {%1, %2};" : "=l"(r) : "r"(__float_as_uint(x)), "r"(__float_as_uint(y)));
    return r;
}
__device__ __forceinline__ unsigned long long dup2(float x) {
    unsigned long long r;
    asm("mov.b64 %0, {%1, %1};" : "=l"(r) : "r"(__float_as_uint(x)));
    return r;
}
__device__ __forceinline__ float2 unpack2(unsigned long long v) {
    unsigned int lo, hi;
    asm("mov.b64 {%0, %1}, %2;" : "=r"(lo), "=r"(hi) : "l"(v));
    return make_float2(__uint_as_float(lo), __uint_as_float(hi));
}
#define FMA2(acc, a2, b2) \
    asm("fma.rn.f32x2 %0, %1, %2, %0;" : "+l"(acc) : "l"(a2), "l"(b2))

// ---------------------------------------------------------------------------
// Kernel: reduced Q/K weights
// ---------------------------------------------------------------------------
__global__ void prep_weights(const float* __restrict__ Wq, const float* __restrict__ bq,
                             const float* __restrict__ Wk, const float* __restrict__ bk) {
    int idx = blockIdx.x * 256 + threadIdx.x;
    if (idx >= 4096) return;
    int set = idx >> 11;
    int m = (idx >> 8) & 7;
    int i = idx & 255;
    const float* W = set ? Wk : Wq;
    float s = 0.f;
    #pragma unroll
    for (int c = 0; c < 32; c++) s += W[(m * 64 + c) * 256 + i];
    if (set) g_Wks[m * 256 + i] = s; else g_Wqs[m * 256 + i] = s;
    if (i == 0) {
        const float* bb = set ? bk : bq;
        float t = 0.f;
        #pragma unroll
        for (int c = 0; c < 32; c++) t += bb[m * 64 + c];
        if (set) g_bks[m] = t; else g_bqs[m] = t;
    }
}

// ---------------------------------------------------------------------------
// Kernel: V-weight prefix tables for the s-half telescope
// ---------------------------------------------------------------------------
__global__ void prep_vweights(const float* __restrict__ Wv, const float* __restrict__ bv) {
    int idx = blockIdx.x * 256 + threadIdx.x; // 0..8191
    if (idx >= 8192) return;
    int c = idx & 31, i = idx >> 5;
    float acc = 0.f;
    #pragma unroll
    for (int m = 0; m < 8; m++) {
        g_WpartT[m][i * 32 + c] = acc;
        acc += Wv[(m * 64 + c) * 256 + i];
    }
    g_WsumT[i * 32 + c] = acc;
    if (i == 0) {
        float s = 0.f;
        #pragma unroll
        for (int m = 0; m < 8; m++) s += bv[m * 64 + c];
        g_BS[c] = s;
    }
}

// ---------------------------------------------------------------------------
// Kernel: row prefix of enc, stored at the 129 telescope endpoints per batch.
// CTA per b, thread = channel i.
// ---------------------------------------------------------------------------
__global__ void __launch_bounds__(256) enc_prefix(const float* __restrict__ enc) {
    int b = blockIdx.x;
    int i = threadIdx.x;
    const float* e = enc + (size_t)b * 400 * 256 + i;
    float* Pn = g_Pn + (size_t)b * 129 * 256;
    Pn[i] = 0.f; // qq = 0
    float acc = 0.f;
    for (int r = 0; r < 400; r++) {
        acc += e[(size_t)r * 256];
        // checkpoint if exists qq with (25qq>>3)-1 == r  <=>  25qq in [8r+8, 8r+16)
        int qq = (8 * r + 32) / 25;
        int v = 25 * qq;
        if (v >= 8 * r + 8 && v < 8 * r + 16)
            Pn[(size_t)qq * 256 + i] = acc;
    }
}

// ---------------------------------------------------------------------------
// Kernel: E[b,qq,c] = Pn[b,qq]·WsumT[:,c] + enc[row R]·WpartT[p][:,c]
// warp per (b,qq), lane = c.
// ---------------------------------------------------------------------------
__global__ void __launch_bounds__(256) e_kernel(const float* __restrict__ enc) {
    int id = blockIdx.x * 8 + (threadIdx.x >> 5);
    if (id >= NB * 129) return;
    int c = threadIdx.x & 31;
    int b = id / 129, qq = id - b * 129;
    const float* Pn = g_Pn + (size_t)id * 256;
    float acc = 0.f;
    for (int i = 0; i < 256; i++) acc += Pn[i] * g_WsumT[i * 32 + c];
    int p = qq & 7;
    if (p) {
        int R = (25 * qq) >> 3;
        const float* er = enc + ((size_t)b * 400 + R) * 256;
        const float* Wp = g_WpartT[p];
        for (int i = 0; i < 256; i++) acc += er[i] * Wp[i * 32 + c];
    }
    g_E[(size_t)id * 32 + c] = acc;
}

// ---------------------------------------------------------------------------
// Kernel: vs_sum[b,h,to,c] = sum_t Wconv[to,t]*U[b,h*16+t,c] + 25*bconv[to]
//   U[q,c] = E[q+1]-E[q] + 3*BS[c] + bv[(q&7)*64+c]
// ---------------------------------------------------------------------------
__global__ void __launch_bounds__(256) vs_assemble(const float* __restrict__ Wconv,
                                                   const float* __restrict__ bconv,
                                                   const float* __restrict__ bv) {
    int idx = blockIdx.x * 256 + threadIdx.x;
    if (idx >= NB * 8 * 32 * 32) return;
    int c = idx & 31;
    int to = (idx >> 5) & 31;
    int h = (idx >> 10) & 7;
    int b = idx >> 13;
    const float* Eb = g_E + (size_t)b * 129 * 32;
    float bs3 = 3.f * g_BS[c];
    float acc = 25.f * bconv[to];
    #pragma unroll
    for (int t = 0; t < 16; t++) {
        int q = h * 16 + t;
        float U = Eb[(q + 1) * 32 + c] - Eb[q * 32 + c] + bs3 + bv[(q & 7) * 64 + c];
        acc += Wconv[to * 16 + t] * U;
    }
    g_vs[idx] = acc;
}

// ---------------------------------------------------------------------------
// Kernel: reduced-weight row GEMM (q and k paths)
// ---------------------------------------------------------------------------
template <int WHICH>
__global__ void __launch_bounds__(256) row_reduce(const float* __restrict__ src) {
    __shared__ float sW[2048];
    for (int i = threadIdx.x; i < 2048; i += 256)
        sW[i] = (WHICH == 0) ? g_Wqs[i] : g_Wks[i];
    __syncthreads();
    int warp = threadIdx.x >> 5, lane = threadIdx.x & 31;
    int R = blockIdx.x * 8 + warp;
    const float* xr = src + (size_t)R * 256;
    float p[8] = {0.f, 0.f, 0.f, 0.f, 0.f, 0.f, 0.f, 0.f};
    for (int i = lane; i < 256; i += 32) {
        float xv = xr[i];
        #pragma unroll
        for (int m = 0; m < 8; m++) p[m] += xv * sW[m * 256 + i];
    }
    #pragma unroll
    for (int m = 0; m < 8; m++) {
        #pragma unroll
        for (int off = 16; off; off >>= 1)
            p[m] += __shfl_down_sync(0xffffffffu, p[m], off);
    }
    if (lane == 0) {
        float* dst = (WHICH == 0) ? g_qs : g_ksp;
        const float* bs = (WHICH == 0) ? g_bqs : g_bks;
        #pragma unroll
        for (int m = 0; m < 8; m++) dst[(size_t)R * 8 + m] = p[m] + bs[m];
    }
}

// ---------------------------------------------------------------------------
// Kernel: K temporal conv
// ---------------------------------------------------------------------------
__global__ void k_conv(const float* __restrict__ Wconv, const float* __restrict__ bconv) {
    int idx = blockIdx.x * blockDim.x + threadIdx.x;
    if (idx >= NB * 6400) return;
    int b = idx / 6400;
    int g = idx - b * 6400;
    int h = g / 800;
    int rem = g - h * 800;
    int to = rem / 25;
    int j = rem - to * 25;
    const float* kp = g_ksp + b * 3200 + h * 400 + j;
    float s = 32.0f * bconv[to];
    #pragma unroll
    for (int t = 0; t < 16; t++) s += Wconv[to * 16 + t] * kp[t * 25];
    g_kss[idx] = s;
}

// ---------------------------------------------------------------------------
// Kernel: t-half V GEMM with packed f32x2 FMA.
// C[r, o'] = enc[r,:]·Wv[wmap(o'),:] + bv[wmap(o')], wmap(o')=(o'>>5)*64+32+(o'&31)
// M=51200, N=256, K=256. Tiles 128x128x8, thread tile 8x8 (4 packed pairs).
// ---------------------------------------------------------------------------
__global__ void __launch_bounds__(256) v_gemm_t(const float* __restrict__ A,
                                                const float* __restrict__ W,
                                                const float* __restrict__ bv) {
    __shared__ float As[8][128];
    __shared__ float Bs[8][128];
    int tm = blockIdx.y, tn = blockIdx.x; // tn in {0,1}
    int tid = threadIdx.x;
    int tr = tid >> 4, tc = tid & 15;
    const float* Ab = A + (size_t)tm * 128 * 256;

    int lrow = tid >> 1, lk = (tid & 1) * 4;
    int wcol = tn * 128 + lrow;
    int wrow = ((wcol >> 5) << 6) + 32 + (wcol & 31);
    const float* Wr = W + (size_t)wrow * 256;
    const float* Ar = Ab + (size_t)lrow * 256;

    unsigned long long acc2[8][4];
    #pragma unroll
    for (int i = 0; i < 8; i++)
        #pragma unroll
        for (int jp = 0; jp < 4; jp++) acc2[i][jp] = 0ull;

    for (int k0 = 0; k0 < 256; k0 += 8) {
        float4 av = *reinterpret_cast<const float4*>(Ar + k0 + lk);
        float4 wv = *reinterpret_cast<const float4*>(Wr + k0 + lk);
        As[lk + 0][lrow] = av.x; As[lk + 1][lrow] = av.y;
        As[lk + 2][lrow] = av.z; As[lk + 3][lrow] = av.w;
        Bs[lk + 0][lrow] = wv.x; Bs[lk + 1][lrow] = wv.y;
        Bs[lk + 2][lrow] = wv.z; Bs[lk + 3][lrow] = wv.w;
        __syncthreads();
        #pragma unroll
        for (int k = 0; k < 8; k++) {
            const float4 a0 = *reinterpret_cast<const float4*>(&As[k][tr * 8]);
            const float4 a1 = *reinterpret_cast<const float4*>(&As[k][tr * 8 + 4]);
            const float4 b0 = *reinterpret_cast<const float4*>(&Bs[k][tc * 8]);
            const float4 b1 = *reinterpret_cast<const float4*>(&Bs[k][tc * 8 + 4]);
            unsigned long long bp0 = pack2(b0.x, b0.y);
            unsigned long long bp1 = pack2(b0.z, b0.w);
            unsigned long long bp2 = pack2(b1.x, b1.y);
            unsigned long long bp3 = pack2(b1.z, b1.w);
            float aa[8] = {a0.x, a0.y, a0.z, a0.w, a1.x, a1.y, a1.z, a1.w};
            #pragma unroll
            for (int i = 0; i < 8; i++) {
                unsigned long long ad = dup2(aa[i]);
                FMA2(acc2[i][0], ad, bp0);
                FMA2(acc2[i][1], ad, bp1);
                FMA2(acc2[i][2], ad, bp2);
                FMA2(acc2[i][3], ad, bp3);
            }
        }
        __syncthreads();
    }

    int gr0 = tm * 128 + tr * 8;
    int gc0 = tn * 128 + tc * 8;
    float bvr[8];
    #pragma unroll
    for (int j = 0; j < 8; j++) {
        int col = gc0 + j;
        bvr[j] = bv[((col >> 5) << 6) + 32 + (col & 31)];
    }
    #pragma unroll
    for (int i = 0; i < 8; i++) {
        float2 r0 = unpack2(acc2[i][0]);
        float2 r1 = unpack2(acc2[i][1]);
        float2 r2 = unpack2(acc2[i][2]);
        float2 r3 = unpack2(acc2[i][3]);
        float* Crow = g_Vt + (size_t)(gr0 + i) * 256 + gc0;
        float4 v0 = make_float4(r0.x + bvr[0], r0.y + bvr[1], r1.x + bvr[2], r1.y + bvr[3]);
        float4 v1 = make_float4(r2.x + bvr[4], r2.y + bvr[5], r3.x + bvr[6], r3.y + bvr[7]);
        *reinterpret_cast<float4*>(Crow) = v0;
        *reinterpret_cast<float4*>(Crow + 4) = v1;
    }
}

// ---------------------------------------------------------------------------
// Kernel: vt reduction from compact t-half V.
// vt[b,h,j,c] = sum_t2 Vt[b*400 + (g>>3)][ (g&7)*32 + c ],  g=400h+25t2+j
// ---------------------------------------------------------------------------
__global__ void __launch_bounds__(256) vt_reduce() {
    int bh = blockIdx.x;
    int b = bh >> 3, h = bh & 7;
    int tid = threadIdx.x;
    const float* Vb = g_Vt + (size_t)b * 400 * 256;
    for (int s = tid; s < 800; s += 256) {
        int j = s >> 5, c = s & 31;
        float acc = 0.f;
        #pragma unroll
        for (int t2 = 0; t2 < 16; t2++) {
            int g = 400 * h + 25 * t2 + j;
            acc += Vb[(size_t)(g >> 3) * 256 + (g & 7) * 32 + c];
        }
        g_vt[(size_t)bh * 800 + s] = acc;
    }
}

// ---------------------------------------------------------------------------
// Kernel: emit output (diag softmax * vs ; vt passthrough)
// ---------------------------------------------------------------------------
__global__ void __launch_bounds__(256) emit_out(const int* __restrict__ mask_s,
                                                float* __restrict__ out) {
    __shared__ float s_qs[800], s_kss[800], s_vs[1024], s_vt[800];
    int bh = blockIdx.x;
    int b = bh >> 3, h = bh & 7;
    int tid = threadIdx.x;
    for (int i = tid; i < 800; i += 256) {
        s_qs[i]  = g_qs[b * 6400 + h * 800 + i];
        s_kss[i] = g_kss[b * 6400 + h * 800 + i];
        s_vt[i]  = g_vt[(size_t)bh * 800 + i];
    }
    for (int i = tid; i < 1024; i += 256) s_vs[i] = g_vs[(size_t)bh * 1024 + i];
    __syncthreads();

    int warp = tid >> 5, lane = tid & 31;
    for (int it = warp; it < 800; it += 8) {
        int to = it / 25, j = it - to * 25;
        float a = s_qs[it];
        float sc;
        if (lane < 25) {
            int mk = mask_s[(to * 25 + j) * 25 + lane];
            sc = mk ? a * s_kss[to * 25 + lane] : -1.0e9f;
        } else {
            sc = -3.0e38f;
        }
        float mx = sc;
        #pragma unroll
        for (int off = 16; off; off >>= 1)
            mx = fmaxf(mx, __shfl_xor_sync(0xffffffffu, mx, off));
        float e = (lane < 25) ? expf(sc - mx) : 0.f;
        float ssum = e;
        #pragma unroll
        for (int off = 16; off; off >>= 1)
            ssum += __shfl_xor_sync(0xffffffffu, ssum, off);
        float diag = __shfl_sync(0xffffffffu, e, j) / ssum;

        int obase = ((b * 32 + to) * 25 + j) * 512 + h * 64;
        out[obase + lane]      = diag * s_vs[to * 32 + lane];
        out[obase + 32 + lane] = s_vt[j * 32 + lane];
    }
}

// ---------------------------------------------------------------------------
extern "C" void kernel_launch(void* const* d_in, const int* in_sizes, int n_in,
                              void* d_out, int out_size) {
    const float* x      = (const float*)d_in[0];
    const float* enc    = (const float*)d_in[1];
    const int*   mask_s = (const int*)d_in[2];
    // d_in[3] = mask_t (unused: temporal softmax rows sum to 1)
    const float* Wq     = (const float*)d_in[4];
    const float* bq     = (const float*)d_in[5];
    const float* Wk     = (const float*)d_in[6];
    const float* bk     = (const float*)d_in[7];
    const float* Wv     = (const float*)d_in[8];
    const float* bv     = (const float*)d_in[9];
    const float* Wconv  = (const float*)d_in[10];
    const float* bconv  = (const float*)d_in[11];
    float* out = (float*)d_out;

    prep_weights<<<16, 256>>>(Wq, bq, Wk, bk);
    prep_vweights<<<32, 256>>>(Wv, bv);
    enc_prefix<<<128, 256>>>(enc);
    row_reduce<0><<<12800, 256>>>(x);
    row_reduce<1><<<6400, 256>>>(enc);
    k_conv<<<3200, 256>>>(Wconv, bconv);
    e_kernel<<<2064, 256>>>(enc);
    vs_assemble<<<4096, 256>>>(Wconv, bconv, bv);
    v_gemm_t<<<dim3(2, 400), 256>>>(enc, Wv, bv);
    vt_reduce<<<1024, 256>>>();
    emit_out<<<1024, 256>>>(mask_s, out);
    (void)in_sizes; (void)n_in; (void)out_size;
}

// round 9
// speedup vs baseline: 1.1133x; 1.1028x over previous
#include <cuda_runtime.h>

// Problem constants
#define NB 128
#define NT 16
#define NTO 32
#define NJ 25

// ---------------------------------------------------------------------------
// Scratch (device globals)
// ---------------------------------------------------------------------------
__device__ float g_Wqs[8 * 256];     // reduced Wq (s-half channel sums) [m][i]
__device__ float g_bqs[8];
__device__ float g_Wks[8 * 256];
__device__ float g_bks[8];
__device__ float g_WsumT[256 * 32];  // [i][c] : sum_m Wv[m*64+c][i]
__device__ float g_WpartT[8][256 * 32]; // [p][i][c] : sum_{m<p} Wv[m*64+c][i]
__device__ float g_BS[32];           // sum_m bv[m*64+c]
__device__ float g_qs[NB * 6400];    // qs_sum  [b][g]
__device__ float g_ksp[NB * 3200];   // ks_pre  [b][g]
__device__ float g_kss[NB * 6400];   // ks_sum
__device__ float g_Pn[NB * 129 * 256];  // prefix rows at endpoints [b][qq][i]
__device__ float g_E[NB * 129 * 32];    // telescoped cums [b][qq][c]
__device__ float g_Vt[(size_t)51200 * 256];  // t-half V GEMM result (compact cols)
__device__ float g_vs[NB * 8 * 32 * 32]; // vs_sum [b][h][to][c]
__device__ float g_vt[NB * 8 * 25 * 32]; // vt_sum [b][h][j][c]

// ---------------------------------------------------------------------------
// f32x2 packed helpers (sm_100+)
// ---------------------------------------------------------------------------
__device__ __forceinline__ unsigned long long dup2(float x) {
    unsigned long long r;
    asm("mov.b64 %0, {%1, %1};" : "=l"(r) : "r"(__float_as_uint(x)));
    return r;
}
__device__ __forceinline__ float2 unpack2(unsigned long long v) {
    unsigned int lo, hi;
    asm("mov.b64 {%0, %1}, %2;" : "=r"(lo), "=r"(hi) : "l"(v));
    return make_float2(__uint_as_float(lo), __uint_as_float(hi));
}
#define FMA2(acc, a2, b2) \
    asm("fma.rn.f32x2 %0, %1, %2, %0;" : "+l"(acc) : "l"(a2), "l"(b2))

// ---------------------------------------------------------------------------
// Kernel: reduced Q/K weights
// ---------------------------------------------------------------------------
__global__ void prep_weights(const float* __restrict__ Wq, const float* __restrict__ bq,
                             const float* __restrict__ Wk, const float* __restrict__ bk) {
    int idx = blockIdx.x * 256 + threadIdx.x;
    if (idx >= 4096) return;
    int set = idx >> 11;
    int m = (idx >> 8) & 7;
    int i = idx & 255;
    const float* W = set ? Wk : Wq;
    float s = 0.f;
    #pragma unroll
    for (int c = 0; c < 32; c++) s += W[(m * 64 + c) * 256 + i];
    if (set) g_Wks[m * 256 + i] = s; else g_Wqs[m * 256 + i] = s;
    if (i == 0) {
        const float* bb = set ? bk : bq;
        float t = 0.f;
        #pragma unroll
        for (int c = 0; c < 32; c++) t += bb[m * 64 + c];
        if (set) g_bks[m] = t; else g_bqs[m] = t;
    }
}

// ---------------------------------------------------------------------------
// Kernel: V-weight prefix tables for the s-half telescope
// ---------------------------------------------------------------------------
__global__ void prep_vweights(const float* __restrict__ Wv, const float* __restrict__ bv) {
    int idx = blockIdx.x * 256 + threadIdx.x; // 0..8191
    if (idx >= 8192) return;
    int c = idx & 31, i = idx >> 5;
    float acc = 0.f;
    #pragma unroll
    for (int m = 0; m < 8; m++) {
        g_WpartT[m][i * 32 + c] = acc;
        acc += Wv[(m * 64 + c) * 256 + i];
    }
    g_WsumT[i * 32 + c] = acc;
    if (i == 0) {
        float s = 0.f;
        #pragma unroll
        for (int m = 0; m < 8; m++) s += bv[m * 64 + c];
        g_BS[c] = s;
    }
}

// ---------------------------------------------------------------------------
// Kernel: row prefix of enc, stored at the 129 telescope endpoints per batch.
// ---------------------------------------------------------------------------
__global__ void __launch_bounds__(256) enc_prefix(const float* __restrict__ enc) {
    int b = blockIdx.x;
    int i = threadIdx.x;
    const float* e = enc + (size_t)b * 400 * 256 + i;
    float* Pn = g_Pn + (size_t)b * 129 * 256;
    Pn[i] = 0.f; // qq = 0
    float acc = 0.f;
    for (int r = 0; r < 400; r++) {
        acc += e[(size_t)r * 256];
        int qq = (8 * r + 32) / 25;
        int v = 25 * qq;
        if (v >= 8 * r + 8 && v < 8 * r + 16)
            Pn[(size_t)qq * 256 + i] = acc;
    }
}

// ---------------------------------------------------------------------------
// Kernel: E[b,qq,c] = Pn[b,qq]·WsumT[:,c] + enc[row R]·WpartT[p][:,c]
// ---------------------------------------------------------------------------
__global__ void __launch_bounds__(256) e_kernel(const float* __restrict__ enc) {
    int id = blockIdx.x * 8 + (threadIdx.x >> 5);
    if (id >= NB * 129) return;
    int c = threadIdx.x & 31;
    int b = id / 129, qq = id - b * 129;
    const float* Pn = g_Pn + (size_t)id * 256;
    float acc = 0.f;
    for (int i = 0; i < 256; i++) acc += Pn[i] * g_WsumT[i * 32 + c];
    int p = qq & 7;
    if (p) {
        int R = (25 * qq) >> 3;
        const float* er = enc + ((size_t)b * 400 + R) * 256;
        const float* Wp = g_WpartT[p];
        for (int i = 0; i < 256; i++) acc += er[i] * Wp[i * 32 + c];
    }
    g_E[(size_t)id * 32 + c] = acc;
}

// ---------------------------------------------------------------------------
// Kernel: vs_sum assembly from telescoped E
// ---------------------------------------------------------------------------
__global__ void __launch_bounds__(256) vs_assemble(const float* __restrict__ Wconv,
                                                   const float* __restrict__ bconv,
                                                   const float* __restrict__ bv) {
    int idx = blockIdx.x * 256 + threadIdx.x;
    if (idx >= NB * 8 * 32 * 32) return;
    int c = idx & 31;
    int to = (idx >> 5) & 31;
    int h = (idx >> 10) & 7;
    int b = idx >> 13;
    const float* Eb = g_E + (size_t)b * 129 * 32;
    float bs3 = 3.f * g_BS[c];
    float acc = 25.f * bconv[to];
    #pragma unroll
    for (int t = 0; t < 16; t++) {
        int q = h * 16 + t;
        float U = Eb[(q + 1) * 32 + c] - Eb[q * 32 + c] + bs3 + bv[(q & 7) * 64 + c];
        acc += Wconv[to * 16 + t] * U;
    }
    g_vs[idx] = acc;
}

// ---------------------------------------------------------------------------
// Kernel: reduced-weight row GEMM, register-resident weights (8 rows/warp)
// ---------------------------------------------------------------------------
template <int WHICH>
__global__ void __launch_bounds__(256) row_reduce_reg(const float* __restrict__ src) {
    int warp = threadIdx.x >> 5, lane = threadIdx.x & 31;
    int W = blockIdx.x * 8 + warp;
    const float* Wtbl = (WHICH == 0) ? g_Wqs : g_Wks;
    const float* btbl = (WHICH == 0) ? g_bqs : g_bks;
    float* dst = (WHICH == 0) ? g_qs : g_ksp;

    float w[8][8];
    #pragma unroll
    for (int m = 0; m < 8; m++) {
        float4 w0 = *reinterpret_cast<const float4*>(Wtbl + m * 256 + 4 * lane);
        float4 w1 = *reinterpret_cast<const float4*>(Wtbl + m * 256 + 128 + 4 * lane);
        w[m][0] = w0.x; w[m][1] = w0.y; w[m][2] = w0.z; w[m][3] = w0.w;
        w[m][4] = w1.x; w[m][5] = w1.y; w[m][6] = w1.z; w[m][7] = w1.w;
    }
    #pragma unroll
    for (int rr = 0; rr < 8; rr++) {
        int R = W * 8 + rr;
        const float* xr = src + (size_t)R * 256;
        float4 a0 = *reinterpret_cast<const float4*>(xr + 4 * lane);
        float4 a1 = *reinterpret_cast<const float4*>(xr + 128 + 4 * lane);
        float p[8];
        #pragma unroll
        for (int m = 0; m < 8; m++) {
            p[m] = a0.x * w[m][0] + a0.y * w[m][1] + a0.z * w[m][2] + a0.w * w[m][3]
                 + a1.x * w[m][4] + a1.y * w[m][5] + a1.z * w[m][6] + a1.w * w[m][7];
        }
        #pragma unroll
        for (int m = 0; m < 8; m++) {
            #pragma unroll
            for (int off = 16; off; off >>= 1)
                p[m] += __shfl_down_sync(0xffffffffu, p[m], off);
        }
        if (lane == 0) {
            #pragma unroll
            for (int m = 0; m < 8; m++) dst[(size_t)R * 8 + m] = p[m] + btbl[m];
        }
    }
}

// ---------------------------------------------------------------------------
// Kernel: K temporal conv
// ---------------------------------------------------------------------------
__global__ void k_conv(const float* __restrict__ Wconv, const float* __restrict__ bconv) {
    int idx = blockIdx.x * blockDim.x + threadIdx.x;
    if (idx >= NB * 6400) return;
    int b = idx / 6400;
    int g = idx - b * 6400;
    int h = g / 800;
    int rem = g - h * 800;
    int to = rem / 25;
    int j = rem - to * 25;
    const float* kp = g_ksp + b * 3200 + h * 400 + j;
    float s = 32.0f * bconv[to];
    #pragma unroll
    for (int t = 0; t < 16; t++) s += Wconv[to * 16 + t] * kp[t * 25];
    g_kss[idx] = s;
}

// ---------------------------------------------------------------------------
// Kernel: t-half V GEMM, packed f32x2 FMA, tile 128x256x8, microtile 8x16.
// C[r, o'] = enc[r,:]·Wv[wmap(o'),:] + bv[wmap(o')], wmap(o')=(o'>>5)*64+32+(o'&31)
// B smem uses skewed layout phys(col) = col + (col>>4)*4 (row stride 320) so
// the per-thread 16-col groups land on distinct banks. b operand pairs are
// read directly as 64-bit values (no pack MOVs); only a is dup2'd.
// Register-prefetch software pipeline hides the per-k0 tile fetch.
// grid = 400 (row tiles), 256 threads, 1 CTA/SM (128 acc regs).
// ---------------------------------------------------------------------------
__global__ void __launch_bounds__(256, 1) v_gemm_t(const float* __restrict__ A,
                                                   const float* __restrict__ W,
                                                   const float* __restrict__ bv) {
    __shared__ float As[8][128];
    __shared__ float Bs[8][320];   // skewed: phys = col + (col>>4)*4
    int tid = threadIdx.x;
    int tm = blockIdx.x;
    int tr = tid >> 4;             // 0..15 -> rows tr*8..tr*8+7
    int tc = tid & 15;             // 0..15 -> cols tc*16..tc*16+15

    // loader mapping
    int lrow = tid >> 1, lk = (tid & 1) * 4;       // A: row lrow, k-offsets lk..lk+3
    int lcol = tid;                                 // B: col lcol (0..255)
    int physcol = lcol + ((lcol >> 4) << 2);
    int wrow = ((lcol >> 5) << 6) + 32 + (lcol & 31);
    const float* Ar = A + ((size_t)tm * 128 + lrow) * 256;
    const float* Wr = W + (size_t)wrow * 256;

    unsigned long long acc2[8][8];
    #pragma unroll
    for (int i = 0; i < 8; i++)
        #pragma unroll
        for (int jp = 0; jp < 8; jp++) acc2[i][jp] = 0ull;

    // prefetch k0 = 0
    float4 pa  = *reinterpret_cast<const float4*>(Ar + lk);
    float4 pb0 = *reinterpret_cast<const float4*>(Wr);
    float4 pb1 = *reinterpret_cast<const float4*>(Wr + 4);

    for (int k0 = 0; k0 < 256; k0 += 8) {
        // commit prefetched tile to smem
        As[lk + 0][lrow] = pa.x; As[lk + 1][lrow] = pa.y;
        As[lk + 2][lrow] = pa.z; As[lk + 3][lrow] = pa.w;
        Bs[0][physcol] = pb0.x; Bs[1][physcol] = pb0.y;
        Bs[2][physcol] = pb0.z; Bs[3][physcol] = pb0.w;
        Bs[4][physcol] = pb1.x; Bs[5][physcol] = pb1.y;
        Bs[6][physcol] = pb1.z; Bs[7][physcol] = pb1.w;
        __syncthreads();

        // prefetch next tile (overlaps compute)
        if (k0 + 8 < 256) {
            pa  = *reinterpret_cast<const float4*>(Ar + k0 + 8 + lk);
            pb0 = *reinterpret_cast<const float4*>(Wr + k0 + 8);
            pb1 = *reinterpret_cast<const float4*>(Wr + k0 + 12);
        }

        #pragma unroll
        for (int k = 0; k < 8; k++) {
            const float4 a0 = *reinterpret_cast<const float4*>(&As[k][tr * 8]);
            const float4 a1 = *reinterpret_cast<const float4*>(&As[k][tr * 8 + 4]);
            const float* bp = &Bs[k][tc * 20];   // phys base of 16-col group
            ulonglong2 bA = *reinterpret_cast<const ulonglong2*>(bp);
            ulonglong2 bB = *reinterpret_cast<const ulonglong2*>(bp + 4);
            ulonglong2 bC = *reinterpret_cast<const ulonglong2*>(bp + 8);
            ulonglong2 bD = *reinterpret_cast<const ulonglong2*>(bp + 12);
            unsigned long long bb[8] = {bA.x, bA.y, bB.x, bB.y, bC.x, bC.y, bD.x, bD.y};
            float aa[8] = {a0.x, a0.y, a0.z, a0.w, a1.x, a1.y, a1.z, a1.w};
            #pragma unroll
            for (int i = 0; i < 8; i++) {
                unsigned long long ad = dup2(aa[i]);
                #pragma unroll
                for (int jp = 0; jp < 8; jp++) FMA2(acc2[i][jp], ad, bb[jp]);
            }
        }
        __syncthreads();
    }

    // epilogue
    int gr0 = tm * 128 + tr * 8;
    int gc0 = tc * 16;
    float bvr[16];
    #pragma unroll
    for (int q = 0; q < 16; q++) {
        int col = gc0 + q;
        bvr[q] = bv[((col >> 5) << 6) + 32 + (col & 31)];
    }
    #pragma unroll
    for (int i = 0; i < 8; i++) {
        float f[16];
        #pragma unroll
        for (int jp = 0; jp < 8; jp++) {
            float2 u = unpack2(acc2[i][jp]);
            f[2 * jp] = u.x + bvr[2 * jp];
            f[2 * jp + 1] = u.y + bvr[2 * jp + 1];
        }
        float* Crow = g_Vt + (size_t)(gr0 + i) * 256 + gc0;
        #pragma unroll
        for (int q = 0; q < 4; q++)
            *reinterpret_cast<float4*>(Crow + q * 4) =
                make_float4(f[4 * q], f[4 * q + 1], f[4 * q + 2], f[4 * q + 3]);
    }
}

// ---------------------------------------------------------------------------
// Kernel: vt reduction from compact t-half V
// ---------------------------------------------------------------------------
__global__ void __launch_bounds__(256) vt_reduce() {
    int bh = blockIdx.x;
    int b = bh >> 3, h = bh & 7;
    int tid = threadIdx.x;
    const float* Vb = g_Vt + (size_t)b * 400 * 256;
    for (int s = tid; s < 800; s += 256) {
        int j = s >> 5, c = s & 31;
        float acc = 0.f;
        #pragma unroll
        for (int t2 = 0; t2 < 16; t2++) {
            int g = 400 * h + 25 * t2 + j;
            acc += Vb[(size_t)(g >> 3) * 256 + (g & 7) * 32 + c];
        }
        g_vt[(size_t)bh * 800 + s] = acc;
    }
}

// ---------------------------------------------------------------------------
// Kernel: emit output (diag softmax * vs ; vt passthrough)
// ---------------------------------------------------------------------------
__global__ void __launch_bounds__(256) emit_out(const int* __restrict__ mask_s,
                                                float* __restrict__ out) {
    __shared__ float s_qs[800], s_kss[800], s_vs[1024], s_vt[800];
    int bh = blockIdx.x;
    int b = bh >> 3, h = bh & 7;
    int tid = threadIdx.x;
    for (int i = tid; i < 800; i += 256) {
        s_qs[i]  = g_qs[b * 6400 + h * 800 + i];
        s_kss[i] = g_kss[b * 6400 + h * 800 + i];
        s_vt[i]  = g_vt[(size_t)bh * 800 + i];
    }
    for (int i = tid; i < 1024; i += 256) s_vs[i] = g_vs[(size_t)bh * 1024 + i];
    __syncthreads();

    int warp = tid >> 5, lane = tid & 31;
    for (int it = warp; it < 800; it += 8) {
        int to = it / 25, j = it - to * 25;
        float a = s_qs[it];
        float sc;
        if (lane < 25) {
            int mk = mask_s[(to * 25 + j) * 25 + lane];
            sc = mk ? a * s_kss[to * 25 + lane] : -1.0e9f;
        } else {
            sc = -3.0e38f;
        }
        float mx = sc;
        #pragma unroll
        for (int off = 16; off; off >>= 1)
            mx = fmaxf(mx, __shfl_xor_sync(0xffffffffu, mx, off));
        float e = (lane < 25) ? expf(sc - mx) : 0.f;
        float ssum = e;
        #pragma unroll
        for (int off = 16; off; off >>= 1)
            ssum += __shfl_xor_sync(0xffffffffu, ssum, off);
        float diag = __shfl_sync(0xffffffffu, e, j) / ssum;

        int obase = ((b * 32 + to) * 25 + j) * 512 + h * 64;
        out[obase + lane]      = diag * s_vs[to * 32 + lane];
        out[obase + 32 + lane] = s_vt[j * 32 + lane];
    }
}

// ---------------------------------------------------------------------------
extern "C" void kernel_launch(void* const* d_in, const int* in_sizes, int n_in,
                              void* d_out, int out_size) {
    const float* x      = (const float*)d_in[0];
    const float* enc    = (const float*)d_in[1];
    const int*   mask_s = (const int*)d_in[2];
    // d_in[3] = mask_t (unused: temporal softmax rows sum to 1)
    const float* Wq     = (const float*)d_in[4];
    const float* bq     = (const float*)d_in[5];
    const float* Wk     = (const float*)d_in[6];
    const float* bk     = (const float*)d_in[7];
    const float* Wv     = (const float*)d_in[8];
    const float* bv     = (const float*)d_in[9];
    const float* Wconv  = (const float*)d_in[10];
    const float* bconv  = (const float*)d_in[11];
    float* out = (float*)d_out;

    prep_weights<<<16, 256>>>(Wq, bq, Wk, bk);
    prep_vweights<<<32, 256>>>(Wv, bv);
    enc_prefix<<<128, 256>>>(enc);
    row_reduce_reg<0><<<1600, 256>>>(x);
    row_reduce_reg<1><<<800, 256>>>(enc);
    k_conv<<<3200, 256>>>(Wconv, bconv);
    e_kernel<<<2064, 256>>>(enc);
    vs_assemble<<<4096, 256>>>(Wconv, bconv, bv);
    v_gemm_t<<<400, 256>>>(enc, Wv, bv);
    vt_reduce<<<1024, 256>>>();
    emit_out<<<1024, 256>>>(mask_s, out);
    (void)in_sizes; (void)n_in; (void)out_size;
}